// round 12
// baseline (speedup 1.0000x reference)
#include <cuda_runtime.h>
#include <cuda_bf16.h>
#include <math.h>
#include <stdint.h>

// ---------------- problem constants ----------------
#define Tn 128
#define Bn 32
#define En 4096
#define Hn 512
#define FOURH 2048
#define TB 4096          // T*B
#define Kc 20
#define START_TAG 18
#define STOP_TAG 19

// ---------------- scratch (device globals; allocation-free) ----------------
__device__ __align__(256) __nv_bfloat16 g_xbf[(size_t)TB * En];
__device__ __align__(256) __nv_bfloat16 g_we2n_bf[(size_t)En * En];
__device__ __align__(256) __nv_bfloat16 g_xnbf[(size_t)TB * En];
__device__ __align__(256) __nv_bfloat16 g_wihf_bf[(size_t)FOURH * En];
__device__ __align__(256) __nv_bfloat16 g_wihb_bf[(size_t)FOURH * En];
__device__ __align__(256) __nv_bfloat16 g_whhf_bf[(size_t)FOURH * Hn];
__device__ __align__(256) __nv_bfloat16 g_whhb_bf[(size_t)FOURH * Hn];
__device__ __align__(256) __nv_bfloat16 g_xgf_bf[(size_t)TB * FOURH];
__device__ __align__(256) __nv_bfloat16 g_xgb_bf[(size_t)TB * FOURH];
__device__ float g_hf[(size_t)TB * Hn];
__device__ float g_hb[(size_t)TB * Hn];
__device__ __align__(256) __nv_bfloat16 g_hping_bf[2][2][Bn * Hn];
__device__ float g_feats[(size_t)Bn * Tn * Kc];

// setup barrier (atomic, once per launch) + per-step arrival counters
__device__ unsigned g_bar2[2] = {0u, 0u};
__device__ volatile unsigned g_gen2[2] = {0u, 0u};
__device__ __align__(256) unsigned g_cnt[2][Tn * 32];   // counter at [t*32]

// ================= helpers ===================================================
__device__ __forceinline__ uint32_t smem_to_u32(const void* p) {
    uint32_t a;
    asm("{ .reg .u64 t; cvta.to.shared.u64 t, %1; cvt.u32.u64 %0, t; }"
        : "=r"(a) : "l"(p));
    return a;
}
#define SW128(o) ((o) ^ (((o) >> 3) & 0x70))

__device__ __forceinline__ void cp_async16(uint32_t dst, const void* src) {
    asm volatile("cp.async.cg.shared.global [%0], [%1], 16;" :: "r"(dst), "l"(src));
}
#define CP_COMMIT() asm volatile("cp.async.commit_group;" ::: "memory")
#define CP_WAIT_1() asm volatile("cp.async.wait_group 1;" ::: "memory")
#define CP_WAIT_0() asm volatile("cp.async.wait_group 0;" ::: "memory")

__device__ __forceinline__ void ldsm_x4(uint32_t addr, uint32_t& r0, uint32_t& r1,
                                        uint32_t& r2, uint32_t& r3) {
    asm volatile("ldmatrix.sync.aligned.m8n8.x4.shared.b16 {%0,%1,%2,%3}, [%4];"
                 : "=r"(r0), "=r"(r1), "=r"(r2), "=r"(r3) : "r"(addr));
}

__device__ __forceinline__ void mma16816(float* d, const uint32_t* a, const uint32_t* b) {
    asm volatile(
        "mma.sync.aligned.m16n8k16.row.col.f32.bf16.bf16.f32 "
        "{%0,%1,%2,%3}, {%4,%5,%6,%7}, {%8,%9}, {%0,%1,%2,%3};"
        : "+f"(d[0]), "+f"(d[1]), "+f"(d[2]), "+f"(d[3])
        : "r"(a[0]), "r"(a[1]), "r"(a[2]), "r"(a[3]), "r"(b[0]), "r"(b[1]));
}

__device__ __forceinline__ uint32_t ldg_cg_u32(const void* p) {
    uint32_t v;
    asm volatile("ld.global.cg.u32 %0, [%1];" : "=r"(v) : "l"(p));
    return v;
}

// ================= HMMA GEMM: C[M,N] = A[M,K]bf16 @ B[N,K]bf16^T + bias ======
// CTA tile 128x128, K-step 64, 3-stage cp.async, 256 threads, 2 CTAs/SM.
#define GSTAGE_BYTES 32768                  // A 16KB + B 16KB
#define GEMM_SMEM_BYTES (3 * GSTAGE_BYTES)  // 96KB

template <bool OUT_BF16, bool DUAL>
__global__ void __launch_bounds__(256, 2)
gemm_hmma(const __nv_bfloat16* __restrict__ Aq, const __nv_bfloat16* __restrict__ Bq0,
          const __nv_bfloat16* __restrict__ Bq1,
          const float* __restrict__ bias0, const float* __restrict__ bias1,
          void* __restrict__ Cout0, void* __restrict__ Cout1,
          int M, int N, int K, int nbx)
{
    extern __shared__ __align__(1024) char smem[];
    const uint32_t sb = smem_to_u32(smem);

    const int tid = threadIdx.x;
    const int wid = tid >> 5;
    const int lane = tid & 31;
    const int warp_m = wid & 3;
    const int warp_n = wid >> 2;            // 0..1
    int bx = blockIdx.x;
    const __nv_bfloat16* Bq = Bq0;
    const float* bias = bias0;
    void* Cout = Cout0;
    if (DUAL && bx >= nbx) {
        bx -= nbx; Bq = Bq1; bias = bias1; Cout = Cout1;
    }
    const int m0 = blockIdx.y * 128;
    const int n0 = bx * 128;
    const int NKT = K / 64;

    const int ldr = tid >> 3;               // 0..31
    const int ldc = tid & 7;

#define G_LOAD(kt) do { \
        if ((kt) < NKT) { \
            const uint32_t st = sb + ((kt) % 3) * GSTAGE_BYTES; \
            int _k0 = (kt) * 64; \
            _Pragma("unroll") \
            for (int _p = 0; _p < 4; _p++) { \
                int _r = ldr + _p * 32; \
                cp_async16(st + SW128(_r * 128 + ldc * 16), \
                           Aq + (size_t)(m0 + _r) * K + _k0 + ldc * 8); \
            } \
            _Pragma("unroll") \
            for (int _p = 0; _p < 4; _p++) { \
                int _r = ldr + _p * 32; \
                cp_async16(st + 16384 + SW128(_r * 128 + ldc * 16), \
                           Bq + (size_t)(n0 + _r) * K + _k0 + ldc * 8); \
            } \
        } \
        CP_COMMIT(); \
    } while (0)

    float d[2][8][4];
#pragma unroll
    for (int mi = 0; mi < 2; mi++)
#pragma unroll
        for (int ni = 0; ni < 8; ni++)
#pragma unroll
            for (int q = 0; q < 4; q++) d[mi][ni][q] = 0.f;

    const int aRow = warp_m * 32 + (lane & 15);
    const int aColB = (lane >> 4) * 16;
    const int bRow = warp_n * 64 + (lane & 7) + (lane >> 4) * 8;
    const int bColB = ((lane >> 3) & 1) * 16;

    G_LOAD(0);
    G_LOAD(1);

    for (int i = 0; i < NKT; i++) {
        CP_WAIT_1();
        __syncthreads();
        G_LOAD(i + 2);

        const uint32_t stA = sb + (i % 3) * GSTAGE_BYTES;
        const uint32_t stB = stA + 16384;
#pragma unroll
        for (int ks = 0; ks < 4; ks++) {
            const int kb = ks * 32;
            uint32_t a[2][4];
#pragma unroll
            for (int mi = 0; mi < 2; mi++)
                ldsm_x4(stA + SW128((aRow + mi * 16) * 128 + kb + aColB),
                        a[mi][0], a[mi][1], a[mi][2], a[mi][3]);
            uint32_t b[8][2];
#pragma unroll
            for (int np = 0; np < 4; np++) {
                uint32_t r0, r1, r2, r3;
                ldsm_x4(stB + SW128((bRow + np * 16) * 128 + kb + bColB),
                        r0, r1, r2, r3);
                b[np * 2][0] = r0; b[np * 2][1] = r1;
                b[np * 2 + 1][0] = r2; b[np * 2 + 1][1] = r3;
            }
#pragma unroll
            for (int mi = 0; mi < 2; mi++)
#pragma unroll
                for (int ni = 0; ni < 8; ni++)
                    mma16816(d[mi][ni], a[mi], b[ni]);
        }
    }

    const int qrow = lane >> 2;
    const int qcol = (lane & 3) * 2;
#pragma unroll
    for (int mi = 0; mi < 2; mi++) {
#pragma unroll
        for (int ni = 0; ni < 8; ni++) {
            const int col = n0 + warp_n * 64 + ni * 8 + qcol;
            const int row = m0 + warp_m * 32 + mi * 16 + qrow;
            const float b0 = bias[col], b1 = bias[col + 1];
            float v00 = d[mi][ni][0] + b0, v01 = d[mi][ni][1] + b1;
            float v10 = d[mi][ni][2] + b0, v11 = d[mi][ni][3] + b1;
            if (OUT_BF16) {
                __nv_bfloat16* C = (__nv_bfloat16*)Cout;
                __nv_bfloat162 p0 = __floats2bfloat162_rn(v00, v01);
                __nv_bfloat162 p1 = __floats2bfloat162_rn(v10, v11);
                *(__nv_bfloat162*)(C + (size_t)row * N + col) = p0;
                *(__nv_bfloat162*)(C + (size_t)(row + 8) * N + col) = p1;
            } else {
                float* C = (float*)Cout;
                *(float2*)(C + (size_t)row * N + col) = make_float2(v00, v01);
                *(float2*)(C + (size_t)(row + 8) * N + col) = make_float2(v10, v11);
            }
        }
    }
}

// ================= fused fp32 -> bf16 conversion (all tensors, 1 launch) ====
#define CVT_BLOCKS 25600
__global__ void __launch_bounds__(256)
cvt_all(const float* __restrict__ x, const float* __restrict__ we2n,
        const float* __restrict__ wihf, const float* __restrict__ wihb,
        const float* __restrict__ whhf, const float* __restrict__ whhb)
{
    int bid = blockIdx.x;
    const float* src;
    __nv_bfloat16* dst;
    if (bid < 8192)       { src = x;    dst = g_xbf; }
    else if (bid < 16384) { src = we2n; dst = g_we2n_bf; bid -= 8192; }
    else if (bid < 20480) { src = wihf; dst = g_wihf_bf; bid -= 16384; }
    else if (bid < 24576) { src = wihb; dst = g_wihb_bf; bid -= 20480; }
    else if (bid < 25088) { src = whhf; dst = g_whhf_bf; bid -= 24576; }
    else                  { src = whhb; dst = g_whhb_bf; bid -= 25088; }

    size_t base = ((size_t)bid * 256 + threadIdx.x) * 8;
    float4 a = *(const float4*)(src + base);
    float4 b = *(const float4*)(src + base + 4);
    union { __nv_bfloat16 h[8]; uint4 v; } u;
    u.h[0] = __float2bfloat16(a.x); u.h[1] = __float2bfloat16(a.y);
    u.h[2] = __float2bfloat16(a.z); u.h[3] = __float2bfloat16(a.w);
    u.h[4] = __float2bfloat16(b.x); u.h[5] = __float2bfloat16(b.y);
    u.h[6] = __float2bfloat16(b.z); u.h[7] = __float2bfloat16(b.w);
    *(uint4*)(dst + base) = u.v;
}

// ---------------- setup barrier (atomic, once per launch) --------------------
__device__ __forceinline__ void grid_barrier_dir(int dir) {
    __syncthreads();
    if (threadIdx.x == 0) {
        unsigned gen = g_gen2[dir];
        __threadfence();
        if (atomicAdd(&g_bar2[dir], 1u) == 63u) {
            g_bar2[dir] = 0u;
            __threadfence();
            g_gen2[dir] = gen + 1u;
        } else {
            while (g_gen2[dir] == gen) { __nanosleep(64); }
            __threadfence();
        }
    }
    __syncthreads();
}

// ---------------- per-step counter barrier -----------------------------------
__device__ __forceinline__ void cnt_arrive(unsigned* c) {
    asm volatile("red.release.gpu.global.add.u32 [%0], %1;"
                 :: "l"(c), "r"(1u) : "memory");
}
__device__ __forceinline__ void cnt_wait(const unsigned* c) {
    if (threadIdx.x < 32) {
        unsigned v;
        int spins = 0;
        do {
            asm volatile("ld.acquire.gpu.global.u32 %0, [%1];" : "=r"(v) : "l"(c));
            if (v >= 64u) break;
            if (++spins > 128) __nanosleep(128);
        } while (true);
    }
    __syncthreads();
}

// ---------------- persistent bidirectional LSTM (HMMA recurrence) -----------
// B (h) fragments loaded DIRECTLY from global (ld.global.cg) in canonical
// m16n8k16 layout — no smem staging of h. psum stride 36 -> conflict-free
// fused reduce+gate.
#define HROWB 1040
#define PSTRIDE 36
#define LSTM_W_BYTES  (32 * HROWB)
#define LSTM_PSUM_BYTES (8 * 32 * PSTRIDE * 4)
#define LSTM_C_BYTES  (32 * 8 * 4)
#define LSTM_XGS_BYTES (32 * 4 * 8 * 2)
#define LSTM_SMEM_BYTES (LSTM_W_BYTES + LSTM_PSUM_BYTES + LSTM_C_BYTES + LSTM_XGS_BYTES)

__global__ void __launch_bounds__(256, 1)
lstm_kernel(const __nv_bfloat16* __restrict__ W_hh_f_bf,
            const __nv_bfloat16* __restrict__ W_hh_b_bf)
{
    extern __shared__ __align__(1024) char smc[];
    __nv_bfloat16* Wsh = (__nv_bfloat16*)smc;
    float* psum = (float*)(smc + LSTM_W_BYTES);
    float* csh  = psum + 8 * 32 * PSTRIDE;
    __nv_bfloat16* xgs = (__nv_bfloat16*)(csh + 32 * 8);
    const uint32_t WshU = smem_to_u32(Wsh);
    const uint32_t xgsU = smem_to_u32(xgs);

    const int tid   = threadIdx.x;
    const int lane  = tid & 31;
    const int ks    = tid >> 5;
    const int dir   = blockIdx.x >> 6;
    const int chunk = blockIdx.x & 63;
    const int j0    = chunk * 8;
    const __nv_bfloat16* xg = dir ? g_xgb_bf : g_xgf_bf;
    const __nv_bfloat16* Whh = dir ? W_hh_b_bf : W_hh_f_bf;
    float* hs        = dir ? g_hb : g_hf;
    unsigned* cnts   = g_cnt[dir];

    for (int v = tid; v < 32 * 64; v += 256) {
        int m = v >> 6, c = v & 63;
        int grow = ((m >> 3) << 9) + j0 + (m & 7);
        uint4 w = *(const uint4*)(Whh + (size_t)grow * Hn + c * 8);
        *(uint4*)((char*)Wsh + m * HROWB + c * 16) = w;
    }
    {
        int b = tid >> 3, jj = tid & 7;
        csh[b * 8 + jj] = 0.f;
        g_hping_bf[dir][0][b * Hn + j0 + jj] = __float2bfloat16(0.f);
    }
    if (tid == 0) {
        asm volatile("st.global.cg.u32 [%0], %1;"
                     :: "l"(cnts + (chunk * 2) * 32), "r"(0u) : "memory");
        asm volatile("st.global.cg.u32 [%0], %1;"
                     :: "l"(cnts + (chunk * 2 + 1) * 32), "r"(0u) : "memory");
    }
    __syncthreads();

    uint32_t afr[2][4][4];
    {
        const int aRow = lane & 15;
        const int aColB = ks * 128 + (lane >> 4) * 16;
#pragma unroll
        for (int mi = 0; mi < 2; mi++)
#pragma unroll
            for (int kk = 0; kk < 4; kk++)
                ldsm_x4(WshU + (mi * 16 + aRow) * HROWB + aColB + kk * 32,
                        afr[mi][kk][0], afr[mi][kk][1], afr[mi][kk][2], afr[mi][kk][3]);
    }
    grid_barrier_dir(dir);   // orders counter resets + h0 init across the grid

    // canonical B-fragment address components: n = nt*8 + lane/4,
    // k = ks*64 + kk*16 + 2*(lane%4)  (b1 at +8)
    const int bN = lane >> 2;            // 0..7
    const int bK = (lane & 3) * 2;       // 0,2,4,6
    const int qrow = lane >> 2;
    const int qcol = (lane & 3) * 2;
    const int pfB = tid >> 2;
    const int pfG = tid & 3;

    for (int t = 0; t < Tn; t++) {
        const int p = t & 1;
        const int tact = dir ? (Tn - 1 - t) : t;

        // prefetch xg (h-independent) so it overlaps the counter wait
        if (tid < 128) {
            cp_async16(xgsU + tid * 16,
                       xg + ((size_t)tact * Bn + pfB) * FOURH + pfG * 512 + j0);
        }
        CP_COMMIT();

        if (t > 0) cnt_wait(cnts + (t - 1) * 32);

        // load ALL B (h) fragments directly from global (L2) — max MLP
        const __nv_bfloat16* hg = g_hping_bf[dir][p];
        uint32_t bfr[4][4][2];           // [kk][nt][reg]
#pragma unroll
        for (int kk = 0; kk < 4; kk++) {
            const int kb = ks * 64 + kk * 16 + bK;
#pragma unroll
            for (int nt = 0; nt < 4; nt++) {
                const __nv_bfloat16* hp = hg + (nt * 8 + bN) * Hn + kb;
                bfr[kk][nt][0] = ldg_cg_u32(hp);
                bfr[kk][nt][1] = ldg_cg_u32(hp + 8);
            }
        }

        float d[2][4][4];
#pragma unroll
        for (int mi = 0; mi < 2; mi++)
#pragma unroll
            for (int ni = 0; ni < 4; ni++)
#pragma unroll
                for (int q = 0; q < 4; q++) d[mi][ni][q] = 0.f;

#pragma unroll
        for (int kk = 0; kk < 4; kk++)
#pragma unroll
            for (int mi = 0; mi < 2; mi++)
#pragma unroll
                for (int ni = 0; ni < 4; ni++)
                    mma16816(d[mi][ni], afr[mi][kk], bfr[kk][ni]);

#pragma unroll
        for (int mi = 0; mi < 2; mi++)
#pragma unroll
            for (int ni = 0; ni < 4; ni++) {
                int r = mi * 16 + qrow;
                int c = ni * 8 + qcol;
                psum[(ks * 32 + r) * PSTRIDE + c]       = d[mi][ni][0];
                psum[(ks * 32 + r) * PSTRIDE + c + 1]   = d[mi][ni][1];
                psum[(ks * 32 + r + 8) * PSTRIDE + c]     = d[mi][ni][2];
                psum[(ks * 32 + r + 8) * PSTRIDE + c + 1] = d[mi][ni][3];
            }
        CP_WAIT_0();                     // xg landed (overlapped with MMA)
        __syncthreads();

        // fused reduce + gate update (conflict-free with PSTRIDE=36)
        float hval;
        int hb, hjj;
        {
            int b = tid >> 3, jj = tid & 7;
            hb = b; hjj = jj;
            float g4[4] = {0.f, 0.f, 0.f, 0.f};
#pragma unroll
            for (int kk = 0; kk < 8; kk++) {
#pragma unroll
                for (int g = 0; g < 4; g++)
                    g4[g] += psum[(kk * 32 + g * 8 + jj) * PSTRIDE + b];
            }
            const __nv_bfloat16* xr = xgs + (b * 4) * 8 + jj;
            float gi = g4[0] + __bfloat162float(xr[0]);
            float gf = g4[1] + __bfloat162float(xr[8]);
            float gg = g4[2] + __bfloat162float(xr[16]);
            float go = g4[3] + __bfloat162float(xr[24]);
            float iv = 1.f / (1.f + expf(-gi));
            float fv = 1.f / (1.f + expf(-gf));
            float gv = tanhf(gg);
            float ov = 1.f / (1.f + expf(-go));
            float c = fv * csh[b * 8 + jj] + iv * gv;
            csh[b * 8 + jj] = c;
            hval = ov * tanhf(c);
            unsigned short hb16 = __bfloat16_as_ushort(__float2bfloat16(hval));
            asm volatile("st.global.cg.u16 [%0], %1;"
                         :: "l"((unsigned short*)&g_hping_bf[dir][p ^ 1][b * Hn + j0 + jj]),
                            "h"(hb16) : "memory");
        }
        __syncthreads();                   // all hping stores issued
        if (tid == 0) cnt_arrive(cnts + t * 32);
        // fp32 history store off the critical inter-CTA path
        hs[((size_t)tact * Bn + hb) * Hn + j0 + hjj] = hval;
    }
}

// ---------------- feats: warp per (t,b) -------------------------------------
__global__ void __launch_bounds__(128)
feats_kernel(const float* __restrict__ W_lin, const float* __restrict__ b_lin)
{
    int warp = threadIdx.x >> 5, lane = threadIdx.x & 31;
    int idx = blockIdx.x * 4 + warp;
    int t = idx >> 5, b = idx & 31;
    const float* hfp = g_hf + (size_t)idx * Hn;
    const float* hbp = g_hb + (size_t)idx * Hn;

    float hreg[16], hbreg[16];
#pragma unroll
    for (int i = 0; i < 16; i++) {
        hreg[i]  = hfp[lane + 32 * i];
        hbreg[i] = hbp[lane + 32 * i];
    }
    for (int k = 0; k < Kc; k++) {
        const float* wl = W_lin + k * (2 * Hn);
        float s = 0.f;
#pragma unroll
        for (int i = 0; i < 16; i++) {
            s += hreg[i]  * wl[lane + 32 * i];
            s += hbreg[i] * wl[512 + lane + 32 * i];
        }
#pragma unroll
        for (int o = 16; o; o >>= 1) s += __shfl_xor_sync(0xffffffffu, s, o);
        if (lane == 0)
            g_feats[((size_t)b * Tn + t) * Kc + k] = s + b_lin[k];
    }
}

// ---------------- CRF: warp per batch ---------------------------------------
__global__ void __launch_bounds__(32)
crf_kernel(const int* __restrict__ tags, const float* __restrict__ trans,
           float* __restrict__ out)
{
    int b = blockIdx.x, lane = threadIdx.x;
    float tr[Kc];
#pragma unroll
    for (int j = 0; j < Kc; j++)
        tr[j] = (lane < Kc) ? trans[lane * Kc + j] : 0.f;

    float alpha = (lane == START_TAG) ? 0.f : -10000.f;
    const float* fb = g_feats + (size_t)b * Tn * Kc;

    for (int t = 0; t < Tn; t++) {
        float v[Kc];
#pragma unroll
        for (int j = 0; j < Kc; j++)
            v[j] = __shfl_sync(0xffffffffu, alpha, j) + tr[j];
        float m = v[0];
#pragma unroll
        for (int j = 1; j < Kc; j++) m = fmaxf(m, v[j]);
        float s = 0.f;
#pragma unroll
        for (int j = 0; j < Kc; j++) s += expf(v[j] - m);
        float e = (lane < Kc) ? fb[t * Kc + lane] : 0.f;
        alpha = m + logf(s) + e;
        if (lane >= Kc) alpha = -3.4e38f;
    }

    float v = (lane < Kc) ? alpha + trans[STOP_TAG * Kc + lane] : -3.4e38f;
    float m = v;
#pragma unroll
    for (int o = 16; o; o >>= 1) m = fmaxf(m, __shfl_xor_sync(0xffffffffu, m, o));
    float se = (lane < Kc) ? expf(v - m) : 0.f;
#pragma unroll
    for (int o = 16; o; o >>= 1) se += __shfl_xor_sync(0xffffffffu, se, o);
    float logZ = m + logf(se);

    const int* tg = tags + b * Tn;
    float ts = 0.f, es = 0.f;
    for (int t = lane; t < Tn; t += 32) {
        int nxt = tg[t];
        int prev = (t == 0) ? START_TAG : tg[t - 1];
        ts += trans[nxt * Kc + prev];
        es += fb[t * Kc + nxt];
    }
    if (lane == 0) ts += trans[STOP_TAG * Kc + tg[Tn - 1]];
#pragma unroll
    for (int o = 16; o; o >>= 1) {
        ts += __shfl_xor_sync(0xffffffffu, ts, o);
        es += __shfl_xor_sync(0xffffffffu, es, o);
    }
    if (lane == 0) out[b] = logZ - (ts + es);
}

// ---------------- launch -----------------------------------------------------
extern "C" void kernel_launch(void* const* d_in, const int* in_sizes, int n_in,
                              void* d_out, int out_size)
{
    const float* x      = (const float*)d_in[0];
    const int*   tags   = (const int*)d_in[1];
    const float* W_e2n  = (const float*)d_in[2];
    const float* b_e2n  = (const float*)d_in[3];
    const float* W_ih_f = (const float*)d_in[4];
    const float* W_hh_f = (const float*)d_in[5];
    const float* b_f    = (const float*)d_in[6];
    const float* W_ih_b = (const float*)d_in[7];
    const float* W_hh_b = (const float*)d_in[8];
    const float* b_b    = (const float*)d_in[9];
    const float* W_lin  = (const float*)d_in[10];
    const float* b_lin  = (const float*)d_in[11];
    const float* trans  = (const float*)d_in[12];
    float* out = (float*)d_out;

    __nv_bfloat16 *xbf, *we2nbf, *xnbf, *wihfbf, *wihbbf, *whhfbf, *whhbbf;
    __nv_bfloat16 *xgf, *xgb;
    cudaGetSymbolAddress((void**)&xbf,    g_xbf);
    cudaGetSymbolAddress((void**)&we2nbf, g_we2n_bf);
    cudaGetSymbolAddress((void**)&xnbf,   g_xnbf);
    cudaGetSymbolAddress((void**)&wihfbf, g_wihf_bf);
    cudaGetSymbolAddress((void**)&wihbbf, g_wihb_bf);
    cudaGetSymbolAddress((void**)&whhfbf, g_whhf_bf);
    cudaGetSymbolAddress((void**)&whhbbf, g_whhb_bf);
    cudaGetSymbolAddress((void**)&xgf,    g_xgf_bf);
    cudaGetSymbolAddress((void**)&xgb,    g_xgb_bf);

    cudaFuncSetAttribute(lstm_kernel,
                         cudaFuncAttributeMaxDynamicSharedMemorySize,
                         LSTM_SMEM_BYTES);
    cudaFuncSetAttribute((const void*)gemm_hmma<true, false>,
                         cudaFuncAttributeMaxDynamicSharedMemorySize,
                         GEMM_SMEM_BYTES);
    cudaFuncSetAttribute((const void*)gemm_hmma<true, true>,
                         cudaFuncAttributeMaxDynamicSharedMemorySize,
                         GEMM_SMEM_BYTES);

    // 0) all fp32 -> bf16 conversions in one launch
    cvt_all<<<CVT_BLOCKS, 256>>>(x, W_e2n, W_ih_f, W_ih_b, W_hh_f, W_hh_b);

    // 1) xn = x @ W_e2n^T + b_e2n  (bf16 out)
    {
        dim3 grid(En / 128, TB / 128);
        gemm_hmma<true, false><<<grid, 256, GEMM_SMEM_BYTES>>>(
            xbf, we2nbf, nullptr, b_e2n, nullptr, xnbf, nullptr, TB, En, En, 0);
    }
    // 2) xg_f / xg_b = xn @ W_ih^T + b  (bf16 out; one fused launch)
    {
        dim3 grid(2 * (FOURH / 128), TB / 128);
        gemm_hmma<true, true><<<grid, 256, GEMM_SMEM_BYTES>>>(
            xnbf, wihfbf, wihbbf, b_f, b_b, xgf, xgb, TB, FOURH, En, FOURH / 128);
    }
    // 3) bidirectional LSTM scan (counter barrier + direct-LDG B fragments)
    lstm_kernel<<<128, 256, LSTM_SMEM_BYTES>>>(whhfbf, whhbbf);

    // 4) feats
    feats_kernel<<<TB / 4, 128>>>(W_lin, b_lin);

    // 5) CRF
    crf_kernel<<<Bn, 32>>>(tags, trans, out);
}

// round 14
// speedup vs baseline: 1.0769x; 1.0769x over previous
#include <cuda_runtime.h>
#include <cuda_bf16.h>
#include <math.h>
#include <stdint.h>

// ---------------- problem constants ----------------
#define Tn 128
#define Bn 32
#define En 4096
#define Hn 512
#define FOURH 2048
#define TB 4096          // T*B
#define Kc 20
#define START_TAG 18
#define STOP_TAG 19

// ---------------- scratch (device globals; allocation-free) ----------------
__device__ __align__(256) __nv_bfloat16 g_xbf[(size_t)TB * En];
__device__ __align__(256) __nv_bfloat16 g_we2n_bf[(size_t)En * En];
__device__ __align__(256) __nv_bfloat16 g_xnbf[(size_t)TB * En];
__device__ __align__(256) __nv_bfloat16 g_wihf_bf[(size_t)FOURH * En];
__device__ __align__(256) __nv_bfloat16 g_wihb_bf[(size_t)FOURH * En];
__device__ __align__(256) __nv_bfloat16 g_whhf_bf[(size_t)FOURH * Hn];
__device__ __align__(256) __nv_bfloat16 g_whhb_bf[(size_t)FOURH * Hn];
__device__ __align__(256) __nv_bfloat16 g_xgf_bf[(size_t)TB * FOURH];
__device__ __align__(256) __nv_bfloat16 g_xgb_bf[(size_t)TB * FOURH];
__device__ __align__(256) __nv_bfloat16 g_hf_bf[(size_t)TB * Hn];
__device__ __align__(256) __nv_bfloat16 g_hb_bf[(size_t)TB * Hn];
__device__ __align__(256) __nv_bfloat16 g_hping_bf[2][2][Bn * Hn];
__device__ float g_feats[(size_t)Bn * Tn * Kc];

// setup barrier (atomic, once per launch) + per-step arrival counters
__device__ unsigned g_bar2[2] = {0u, 0u};
__device__ volatile unsigned g_gen2[2] = {0u, 0u};
__device__ __align__(256) unsigned g_cnt[2][Tn * 32];   // counter at [t*32]

// ================= helpers ===================================================
__device__ __forceinline__ uint32_t smem_to_u32(const void* p) {
    uint32_t a;
    asm("{ .reg .u64 t; cvta.to.shared.u64 t, %1; cvt.u32.u64 %0, t; }"
        : "=r"(a) : "l"(p));
    return a;
}
#define SW128(o) ((o) ^ (((o) >> 3) & 0x70))

__device__ __forceinline__ void cp_async16(uint32_t dst, const void* src) {
    asm volatile("cp.async.cg.shared.global [%0], [%1], 16;" :: "r"(dst), "l"(src));
}
#define CP_COMMIT() asm volatile("cp.async.commit_group;" ::: "memory")
#define CP_WAIT_1() asm volatile("cp.async.wait_group 1;" ::: "memory")
#define CP_WAIT_0() asm volatile("cp.async.wait_group 0;" ::: "memory")

__device__ __forceinline__ void ldsm_x4(uint32_t addr, uint32_t& r0, uint32_t& r1,
                                        uint32_t& r2, uint32_t& r3) {
    asm volatile("ldmatrix.sync.aligned.m8n8.x4.shared.b16 {%0,%1,%2,%3}, [%4];"
                 : "=r"(r0), "=r"(r1), "=r"(r2), "=r"(r3) : "r"(addr));
}

__device__ __forceinline__ void mma16816(float* d, const uint32_t* a, const uint32_t* b) {
    asm volatile(
        "mma.sync.aligned.m16n8k16.row.col.f32.bf16.bf16.f32 "
        "{%0,%1,%2,%3}, {%4,%5,%6,%7}, {%8,%9}, {%0,%1,%2,%3};"
        : "+f"(d[0]), "+f"(d[1]), "+f"(d[2]), "+f"(d[3])
        : "r"(a[0]), "r"(a[1]), "r"(a[2]), "r"(a[3]), "r"(b[0]), "r"(b[1]));
}

// ================= HMMA GEMM: C[M,N] = A[M,K]bf16 @ B[N,K]bf16^T + bias ======
// CTA tile 128x128, K-step 64, 3-stage cp.async, 256 threads, 2 CTAs/SM.
#define GSTAGE_BYTES 32768                  // A 16KB + B 16KB
#define GEMM_SMEM_BYTES (3 * GSTAGE_BYTES)  // 96KB

template <bool OUT_BF16, bool DUAL>
__global__ void __launch_bounds__(256, 2)
gemm_hmma(const __nv_bfloat16* __restrict__ Aq, const __nv_bfloat16* __restrict__ Bq0,
          const __nv_bfloat16* __restrict__ Bq1,
          const float* __restrict__ bias0, const float* __restrict__ bias1,
          void* __restrict__ Cout0, void* __restrict__ Cout1,
          int M, int N, int K, int nbx)
{
    extern __shared__ __align__(1024) char smem[];
    const uint32_t sb = smem_to_u32(smem);

    const int tid = threadIdx.x;
    const int wid = tid >> 5;
    const int lane = tid & 31;
    const int warp_m = wid & 3;
    const int warp_n = wid >> 2;            // 0..1
    int bx = blockIdx.x;
    const __nv_bfloat16* Bq = Bq0;
    const float* bias = bias0;
    void* Cout = Cout0;
    if (DUAL && bx >= nbx) {
        bx -= nbx; Bq = Bq1; bias = bias1; Cout = Cout1;
    }
    const int m0 = blockIdx.y * 128;
    const int n0 = bx * 128;
    const int NKT = K / 64;

    const int ldr = tid >> 3;               // 0..31
    const int ldc = tid & 7;

#define G_LOAD(kt) do { \
        if ((kt) < NKT) { \
            const uint32_t st = sb + ((kt) % 3) * GSTAGE_BYTES; \
            int _k0 = (kt) * 64; \
            _Pragma("unroll") \
            for (int _p = 0; _p < 4; _p++) { \
                int _r = ldr + _p * 32; \
                cp_async16(st + SW128(_r * 128 + ldc * 16), \
                           Aq + (size_t)(m0 + _r) * K + _k0 + ldc * 8); \
            } \
            _Pragma("unroll") \
            for (int _p = 0; _p < 4; _p++) { \
                int _r = ldr + _p * 32; \
                cp_async16(st + 16384 + SW128(_r * 128 + ldc * 16), \
                           Bq + (size_t)(n0 + _r) * K + _k0 + ldc * 8); \
            } \
        } \
        CP_COMMIT(); \
    } while (0)

    float d[2][8][4];
#pragma unroll
    for (int mi = 0; mi < 2; mi++)
#pragma unroll
        for (int ni = 0; ni < 8; ni++)
#pragma unroll
            for (int q = 0; q < 4; q++) d[mi][ni][q] = 0.f;

    const int aRow = warp_m * 32 + (lane & 15);
    const int aColB = (lane >> 4) * 16;
    const int bRow = warp_n * 64 + (lane & 7) + (lane >> 4) * 8;
    const int bColB = ((lane >> 3) & 1) * 16;

    G_LOAD(0);
    G_LOAD(1);

    for (int i = 0; i < NKT; i++) {
        CP_WAIT_1();
        __syncthreads();
        G_LOAD(i + 2);

        const uint32_t stA = sb + (i % 3) * GSTAGE_BYTES;
        const uint32_t stB = stA + 16384;
#pragma unroll
        for (int ks = 0; ks < 4; ks++) {
            const int kb = ks * 32;
            uint32_t a[2][4];
#pragma unroll
            for (int mi = 0; mi < 2; mi++)
                ldsm_x4(stA + SW128((aRow + mi * 16) * 128 + kb + aColB),
                        a[mi][0], a[mi][1], a[mi][2], a[mi][3]);
            uint32_t b[8][2];
#pragma unroll
            for (int np = 0; np < 4; np++) {
                uint32_t r0, r1, r2, r3;
                ldsm_x4(stB + SW128((bRow + np * 16) * 128 + kb + bColB),
                        r0, r1, r2, r3);
                b[np * 2][0] = r0; b[np * 2][1] = r1;
                b[np * 2 + 1][0] = r2; b[np * 2 + 1][1] = r3;
            }
#pragma unroll
            for (int mi = 0; mi < 2; mi++)
#pragma unroll
                for (int ni = 0; ni < 8; ni++)
                    mma16816(d[mi][ni], a[mi], b[ni]);
        }
    }

    const int qrow = lane >> 2;
    const int qcol = (lane & 3) * 2;
#pragma unroll
    for (int mi = 0; mi < 2; mi++) {
#pragma unroll
        for (int ni = 0; ni < 8; ni++) {
            const int col = n0 + warp_n * 64 + ni * 8 + qcol;
            const int row = m0 + warp_m * 32 + mi * 16 + qrow;
            const float b0 = bias[col], b1 = bias[col + 1];
            float v00 = d[mi][ni][0] + b0, v01 = d[mi][ni][1] + b1;
            float v10 = d[mi][ni][2] + b0, v11 = d[mi][ni][3] + b1;
            if (OUT_BF16) {
                __nv_bfloat16* C = (__nv_bfloat16*)Cout;
                __nv_bfloat162 p0 = __floats2bfloat162_rn(v00, v01);
                __nv_bfloat162 p1 = __floats2bfloat162_rn(v10, v11);
                *(__nv_bfloat162*)(C + (size_t)row * N + col) = p0;
                *(__nv_bfloat162*)(C + (size_t)(row + 8) * N + col) = p1;
            } else {
                float* C = (float*)Cout;
                *(float2*)(C + (size_t)row * N + col) = make_float2(v00, v01);
                *(float2*)(C + (size_t)(row + 8) * N + col) = make_float2(v10, v11);
            }
        }
    }
}

// ================= fused fp32 -> bf16 conversion (all tensors, 1 launch) ====
#define CVT_BLOCKS 25600
__global__ void __launch_bounds__(256)
cvt_all(const float* __restrict__ x, const float* __restrict__ we2n,
        const float* __restrict__ wihf, const float* __restrict__ wihb,
        const float* __restrict__ whhf, const float* __restrict__ whhb)
{
    int bid = blockIdx.x;
    const float* src;
    __nv_bfloat16* dst;
    if (bid < 8192)       { src = x;    dst = g_xbf; }
    else if (bid < 16384) { src = we2n; dst = g_we2n_bf; bid -= 8192; }
    else if (bid < 20480) { src = wihf; dst = g_wihf_bf; bid -= 16384; }
    else if (bid < 24576) { src = wihb; dst = g_wihb_bf; bid -= 20480; }
    else if (bid < 25088) { src = whhf; dst = g_whhf_bf; bid -= 24576; }
    else                  { src = whhb; dst = g_whhb_bf; bid -= 25088; }

    size_t base = ((size_t)bid * 256 + threadIdx.x) * 8;
    float4 a = *(const float4*)(src + base);
    float4 b = *(const float4*)(src + base + 4);
    union { __nv_bfloat16 h[8]; uint4 v; } u;
    u.h[0] = __float2bfloat16(a.x); u.h[1] = __float2bfloat16(a.y);
    u.h[2] = __float2bfloat16(a.z); u.h[3] = __float2bfloat16(a.w);
    u.h[4] = __float2bfloat16(b.x); u.h[5] = __float2bfloat16(b.y);
    u.h[6] = __float2bfloat16(b.z); u.h[7] = __float2bfloat16(b.w);
    *(uint4*)(dst + base) = u.v;
}

// ---------------- setup barrier (atomic, once per launch) --------------------
__device__ __forceinline__ void grid_barrier_dir(int dir) {
    __syncthreads();
    if (threadIdx.x == 0) {
        unsigned gen = g_gen2[dir];
        __threadfence();
        if (atomicAdd(&g_bar2[dir], 1u) == 63u) {
            g_bar2[dir] = 0u;
            __threadfence();
            g_gen2[dir] = gen + 1u;
        } else {
            while (g_gen2[dir] == gen) { __nanosleep(64); }
            __threadfence();
        }
    }
    __syncthreads();
}

// ---------------- per-step counter barrier -----------------------------------
__device__ __forceinline__ void cnt_arrive(unsigned* c) {
    asm volatile("red.release.gpu.global.add.u32 [%0], %1;"
                 :: "l"(c), "r"(1u) : "memory");
}
__device__ __forceinline__ void cnt_wait(const unsigned* c) {
    if (threadIdx.x < 32) {
        unsigned v;
        int spins = 0;
        do {
            asm volatile("ld.acquire.gpu.global.u32 %0, [%1];" : "=r"(v) : "l"(c));
            if (v >= 64u) break;
            if (++spins > 128) __nanosleep(128);
        } while (true);
    }
    __syncthreads();
}

// ---------------- persistent bidirectional LSTM (HMMA recurrence) -----------
// R11 design: h staged via cp.async into 1040B-padded smem rows + ldsm,
// psum stride 36 -> conflict-free fused reduce+gate. h history stored bf16.
#define HROWB 1040
#define PSTRIDE 36
#define LSTM_W_BYTES  (32 * HROWB)
#define LSTM_H_BYTES  (32 * HROWB)
#define LSTM_PSUM_BYTES (8 * 32 * PSTRIDE * 4)
#define LSTM_C_BYTES  (32 * 8 * 4)
#define LSTM_XGS_BYTES (32 * 4 * 8 * 2)
#define LSTM_SMEM_BYTES (LSTM_W_BYTES + LSTM_H_BYTES + LSTM_PSUM_BYTES + \
                         LSTM_C_BYTES + LSTM_XGS_BYTES)

__global__ void __launch_bounds__(256, 1)
lstm_kernel(const __nv_bfloat16* __restrict__ W_hh_f_bf,
            const __nv_bfloat16* __restrict__ W_hh_b_bf)
{
    extern __shared__ __align__(1024) char smc[];
    __nv_bfloat16* Wsh = (__nv_bfloat16*)smc;
    __nv_bfloat16* hsh = (__nv_bfloat16*)(smc + LSTM_W_BYTES);
    float* psum = (float*)(smc + LSTM_W_BYTES + LSTM_H_BYTES);
    float* csh  = psum + 8 * 32 * PSTRIDE;
    __nv_bfloat16* xgs = (__nv_bfloat16*)(csh + 32 * 8);
    const uint32_t WshU = smem_to_u32(Wsh);
    const uint32_t hshU = smem_to_u32(hsh);
    const uint32_t xgsU = smem_to_u32(xgs);

    const int tid   = threadIdx.x;
    const int lane  = tid & 31;
    const int ks    = tid >> 5;
    const int dir   = blockIdx.x >> 6;
    const int chunk = blockIdx.x & 63;
    const int j0    = chunk * 8;
    const __nv_bfloat16* xg = dir ? g_xgb_bf : g_xgf_bf;
    const __nv_bfloat16* Whh = dir ? W_hh_b_bf : W_hh_f_bf;
    __nv_bfloat16* hs = dir ? g_hb_bf : g_hf_bf;
    unsigned* cnts   = g_cnt[dir];

    for (int v = tid; v < 32 * 64; v += 256) {
        int m = v >> 6, c = v & 63;
        int grow = ((m >> 3) << 9) + j0 + (m & 7);
        uint4 w = *(const uint4*)(Whh + (size_t)grow * Hn + c * 8);
        *(uint4*)((char*)Wsh + m * HROWB + c * 16) = w;
    }
    {
        int b = tid >> 3, jj = tid & 7;
        csh[b * 8 + jj] = 0.f;
        g_hping_bf[dir][0][b * Hn + j0 + jj] = __float2bfloat16(0.f);
    }
    if (tid == 0) {
        asm volatile("st.global.cg.u32 [%0], %1;"
                     :: "l"(cnts + (chunk * 2) * 32), "r"(0u) : "memory");
        asm volatile("st.global.cg.u32 [%0], %1;"
                     :: "l"(cnts + (chunk * 2 + 1) * 32), "r"(0u) : "memory");
    }
    __syncthreads();

    uint32_t afr[2][4][4];
    {
        const int aRow = lane & 15;
        const int aColB = ks * 128 + (lane >> 4) * 16;
#pragma unroll
        for (int mi = 0; mi < 2; mi++)
#pragma unroll
            for (int kk = 0; kk < 4; kk++)
                ldsm_x4(WshU + (mi * 16 + aRow) * HROWB + aColB + kk * 32,
                        afr[mi][kk][0], afr[mi][kk][1], afr[mi][kk][2], afr[mi][kk][3]);
    }
    grid_barrier_dir(dir);   // orders counter resets + h0 init across the grid

    const int bRowBase = (lane & 7) + ((lane >> 4) << 3);
    const int bColB = ks * 128 + (((lane >> 3) & 1) << 4);
    const int qrow = lane >> 2;
    const int qcol = (lane & 3) * 2;
    const int pfB = tid >> 2;
    const int pfG = tid & 3;

    for (int t = 0; t < Tn; t++) {
        const int p = t & 1;
        const int tact = dir ? (Tn - 1 - t) : t;

        // prefetch xg (h-independent) so it overlaps the counter wait
        if (tid < 128) {
            cp_async16(xgsU + tid * 16,
                       xg + ((size_t)tact * Bn + pfB) * FOURH + pfG * 512 + j0);
        }
        CP_COMMIT();

        if (t > 0) cnt_wait(cnts + (t - 1) * 32);

        // stage h (bf16, 32x512) into padded smem rows
        const __nv_bfloat16* hg = g_hping_bf[dir][p];
#pragma unroll
        for (int u = 0; u < 8; u++) {
            int idx = tid + u * 256;
            int b = idx >> 6, c = idx & 63;
            cp_async16(hshU + b * HROWB + c * 16, hg + b * Hn + c * 8);
        }
        CP_COMMIT();
        CP_WAIT_0();
        __syncthreads();

        float d[2][4][4];
#pragma unroll
        for (int mi = 0; mi < 2; mi++)
#pragma unroll
            for (int ni = 0; ni < 4; ni++)
#pragma unroll
                for (int q = 0; q < 4; q++) d[mi][ni][q] = 0.f;

#pragma unroll
        for (int kk = 0; kk < 4; kk++) {
            uint32_t bfr[4][2];
#pragma unroll
            for (int nt = 0; nt < 2; nt++) {
                uint32_t r0, r1, r2, r3;
                ldsm_x4(hshU + (bRowBase + nt * 16) * HROWB + bColB + kk * 32,
                        r0, r1, r2, r3);
                bfr[nt * 2][0] = r0; bfr[nt * 2][1] = r1;
                bfr[nt * 2 + 1][0] = r2; bfr[nt * 2 + 1][1] = r3;
            }
#pragma unroll
            for (int mi = 0; mi < 2; mi++)
#pragma unroll
                for (int ni = 0; ni < 4; ni++)
                    mma16816(d[mi][ni], afr[mi][kk], bfr[ni]);
        }

#pragma unroll
        for (int mi = 0; mi < 2; mi++)
#pragma unroll
            for (int ni = 0; ni < 4; ni++) {
                int r = mi * 16 + qrow;
                int c = ni * 8 + qcol;
                psum[(ks * 32 + r) * PSTRIDE + c]       = d[mi][ni][0];
                psum[(ks * 32 + r) * PSTRIDE + c + 1]   = d[mi][ni][1];
                psum[(ks * 32 + r + 8) * PSTRIDE + c]     = d[mi][ni][2];
                psum[(ks * 32 + r + 8) * PSTRIDE + c + 1] = d[mi][ni][3];
            }
        __syncthreads();

        // fused reduce + gate update (conflict-free with PSTRIDE=36)
        float hval;
        int hb, hjj;
        {
            int b = tid >> 3, jj = tid & 7;
            hb = b; hjj = jj;
            float g4[4] = {0.f, 0.f, 0.f, 0.f};
#pragma unroll
            for (int kk = 0; kk < 8; kk++) {
#pragma unroll
                for (int g = 0; g < 4; g++)
                    g4[g] += psum[(kk * 32 + g * 8 + jj) * PSTRIDE + b];
            }
            const __nv_bfloat16* xr = xgs + (b * 4) * 8 + jj;
            float gi = g4[0] + __bfloat162float(xr[0]);
            float gf = g4[1] + __bfloat162float(xr[8]);
            float gg = g4[2] + __bfloat162float(xr[16]);
            float go = g4[3] + __bfloat162float(xr[24]);
            float iv = 1.f / (1.f + expf(-gi));
            float fv = 1.f / (1.f + expf(-gf));
            float gv = tanhf(gg);
            float ov = 1.f / (1.f + expf(-go));
            float c = fv * csh[b * 8 + jj] + iv * gv;
            csh[b * 8 + jj] = c;
            hval = ov * tanhf(c);
            unsigned short hb16 = __bfloat16_as_ushort(__float2bfloat16(hval));
            asm volatile("st.global.cg.u16 [%0], %1;"
                         :: "l"((unsigned short*)&g_hping_bf[dir][p ^ 1][b * Hn + j0 + jj]),
                            "h"(hb16) : "memory");
        }
        __syncthreads();                   // all hping stores issued
        if (tid == 0) cnt_arrive(cnts + t * 32);
        // bf16 history store (consumed only by feats) off the critical path
        hs[((size_t)tact * Bn + hb) * Hn + j0 + hjj] = __float2bfloat16(hval);
    }
}

// ---------------- feats: warp computes 4 (t,b) pairs (W_lin amortized) -------
// grid 256 x 128 threads; warp w handles idx = bid*16 + w*4 + {0..3}.
__global__ void __launch_bounds__(128)
feats_kernel(const float* __restrict__ W_lin, const float* __restrict__ b_lin)
{
    const int warp = threadIdx.x >> 5, lane = threadIdx.x & 31;
    const int idx0 = blockIdx.x * 16 + warp * 4;

    // load h (bf16) for 4 idx: per lane 8 bf162 words each for hf and hb
    uint32_t hf2[4][8], hb2[4][8];
#pragma unroll
    for (int j = 0; j < 4; j++) {
        const uint32_t* hfp = (const uint32_t*)(g_hf_bf + (size_t)(idx0 + j) * Hn);
        const uint32_t* hbp = (const uint32_t*)(g_hb_bf + (size_t)(idx0 + j) * Hn);
#pragma unroll
        for (int i = 0; i < 8; i++) {
            hf2[j][i] = hfp[lane + 32 * i];
            hb2[j][i] = hbp[lane + 32 * i];
        }
    }

    for (int k = 0; k < Kc; k++) {
        const float* wl = W_lin + k * (2 * Hn);
        float s[4] = {0.f, 0.f, 0.f, 0.f};
#pragma unroll
        for (int i = 0; i < 8; i++) {
            float2 wf = *(const float2*)(wl + 2 * (lane + 32 * i));
            float2 wb = *(const float2*)(wl + 512 + 2 * (lane + 32 * i));
#pragma unroll
            for (int j = 0; j < 4; j++) {
                __nv_bfloat162 hf = *(__nv_bfloat162*)&hf2[j][i];
                __nv_bfloat162 hb = *(__nv_bfloat162*)&hb2[j][i];
                s[j] += wf.x * __bfloat162float(hf.x) + wf.y * __bfloat162float(hf.y);
                s[j] += wb.x * __bfloat162float(hb.x) + wb.y * __bfloat162float(hb.y);
            }
        }
        // full-warp butterfly reductions (uniform control flow)
#pragma unroll
        for (int j = 0; j < 4; j++) {
#pragma unroll
            for (int o = 16; o; o >>= 1) s[j] += __shfl_xor_sync(0xffffffffu, s[j], o);
        }
        if (lane < 4) {
            int idx = idx0 + lane;           // t*32+b
            int t = idx >> 5, b = idx & 31;
            g_feats[((size_t)b * Tn + t) * Kc + k] = s[lane] + b_lin[k];
        }
    }
}

// ---------------- CRF: warp per batch ---------------------------------------
__global__ void __launch_bounds__(32)
crf_kernel(const int* __restrict__ tags, const float* __restrict__ trans,
           float* __restrict__ out)
{
    int b = blockIdx.x, lane = threadIdx.x;
    float tr[Kc];
#pragma unroll
    for (int j = 0; j < Kc; j++)
        tr[j] = (lane < Kc) ? trans[lane * Kc + j] : 0.f;

    float alpha = (lane == START_TAG) ? 0.f : -10000.f;
    const float* fb = g_feats + (size_t)b * Tn * Kc;

    for (int t = 0; t < Tn; t++) {
        float v[Kc];
#pragma unroll
        for (int j = 0; j < Kc; j++)
            v[j] = __shfl_sync(0xffffffffu, alpha, j) + tr[j];
        float m = v[0];
#pragma unroll
        for (int j = 1; j < Kc; j++) m = fmaxf(m, v[j]);
        float s = 0.f;
#pragma unroll
        for (int j = 0; j < Kc; j++) s += expf(v[j] - m);
        float e = (lane < Kc) ? fb[t * Kc + lane] : 0.f;
        alpha = m + logf(s) + e;
        if (lane >= Kc) alpha = -3.4e38f;
    }

    float v = (lane < Kc) ? alpha + trans[STOP_TAG * Kc + lane] : -3.4e38f;
    float m = v;
#pragma unroll
    for (int o = 16; o; o >>= 1) m = fmaxf(m, __shfl_xor_sync(0xffffffffu, m, o));
    float se = (lane < Kc) ? expf(v - m) : 0.f;
#pragma unroll
    for (int o = 16; o; o >>= 1) se += __shfl_xor_sync(0xffffffffu, se, o);
    float logZ = m + logf(se);

    const int* tg = tags + b * Tn;
    float ts = 0.f, es = 0.f;
    for (int t = lane; t < Tn; t += 32) {
        int nxt = tg[t];
        int prev = (t == 0) ? START_TAG : tg[t - 1];
        ts += trans[nxt * Kc + prev];
        es += fb[t * Kc + nxt];
    }
    if (lane == 0) ts += trans[STOP_TAG * Kc + tg[Tn - 1]];
#pragma unroll
    for (int o = 16; o; o >>= 1) {
        ts += __shfl_xor_sync(0xffffffffu, ts, o);
        es += __shfl_xor_sync(0xffffffffu, es, o);
    }
    if (lane == 0) out[b] = logZ - (ts + es);
}

// ---------------- launch -----------------------------------------------------
extern "C" void kernel_launch(void* const* d_in, const int* in_sizes, int n_in,
                              void* d_out, int out_size)
{
    const float* x      = (const float*)d_in[0];
    const int*   tags   = (const int*)d_in[1];
    const float* W_e2n  = (const float*)d_in[2];
    const float* b_e2n  = (const float*)d_in[3];
    const float* W_ih_f = (const float*)d_in[4];
    const float* W_hh_f = (const float*)d_in[5];
    const float* b_f    = (const float*)d_in[6];
    const float* W_ih_b = (const float*)d_in[7];
    const float* W_hh_b = (const float*)d_in[8];
    const float* b_b    = (const float*)d_in[9];
    const float* W_lin  = (const float*)d_in[10];
    const float* b_lin  = (const float*)d_in[11];
    const float* trans  = (const float*)d_in[12];
    float* out = (float*)d_out;

    __nv_bfloat16 *xbf, *we2nbf, *xnbf, *wihfbf, *wihbbf, *whhfbf, *whhbbf;
    __nv_bfloat16 *xgf, *xgb;
    cudaGetSymbolAddress((void**)&xbf,    g_xbf);
    cudaGetSymbolAddress((void**)&we2nbf, g_we2n_bf);
    cudaGetSymbolAddress((void**)&xnbf,   g_xnbf);
    cudaGetSymbolAddress((void**)&wihfbf, g_wihf_bf);
    cudaGetSymbolAddress((void**)&wihbbf, g_wihb_bf);
    cudaGetSymbolAddress((void**)&whhfbf, g_whhf_bf);
    cudaGetSymbolAddress((void**)&whhbbf, g_whhb_bf);
    cudaGetSymbolAddress((void**)&xgf,    g_xgf_bf);
    cudaGetSymbolAddress((void**)&xgb,    g_xgb_bf);

    cudaFuncSetAttribute(lstm_kernel,
                         cudaFuncAttributeMaxDynamicSharedMemorySize,
                         LSTM_SMEM_BYTES);
    cudaFuncSetAttribute((const void*)gemm_hmma<true, false>,
                         cudaFuncAttributeMaxDynamicSharedMemorySize,
                         GEMM_SMEM_BYTES);
    cudaFuncSetAttribute((const void*)gemm_hmma<true, true>,
                         cudaFuncAttributeMaxDynamicSharedMemorySize,
                         GEMM_SMEM_BYTES);

    // 0) all fp32 -> bf16 conversions in one launch
    cvt_all<<<CVT_BLOCKS, 256>>>(x, W_e2n, W_ih_f, W_ih_b, W_hh_f, W_hh_b);

    // 1) xn = x @ W_e2n^T + b_e2n  (bf16 out)
    {
        dim3 grid(En / 128, TB / 128);
        gemm_hmma<true, false><<<grid, 256, GEMM_SMEM_BYTES>>>(
            xbf, we2nbf, nullptr, b_e2n, nullptr, xnbf, nullptr, TB, En, En, 0);
    }
    // 2) xg_f / xg_b = xn @ W_ih^T + b  (bf16 out; one fused launch)
    {
        dim3 grid(2 * (FOURH / 128), TB / 128);
        gemm_hmma<true, true><<<grid, 256, GEMM_SMEM_BYTES>>>(
            xnbf, wihfbf, wihbbf, b_f, b_b, xgf, xgb, TB, FOURH, En, FOURH / 128);
    }
    // 3) bidirectional LSTM scan (R11 design + bf16 h history)
    lstm_kernel<<<128, 256, LSTM_SMEM_BYTES>>>(whhfbf, whhbbf);

    // 4) feats (W_lin amortized over 4 pairs per warp)
    feats_kernel<<<256, 128>>>(W_lin, b_lin);

    // 5) CRF
    crf_kernel<<<Bn, 32>>>(tags, trans, out);
}